// round 3
// baseline (speedup 1.0000x reference)
#include <cuda_runtime.h>
#include <cuda_bf16.h>

#define N_NODES 50000
#define N_EDGES 800000
#define D 128
#define BM 128
#define KC 32
#define SSTRIDE 33

// ---------------- scratch (device globals; 16B-aligned for float4 use) -------
__device__ __align__(16) int   g_deg[N_NODES];
__device__ __align__(16) int   g_off[N_NODES + 1];
__device__ __align__(16) int   g_cur[N_NODES];
__device__ __align__(16) int   g_ssrc[N_EDGES];
__device__ __align__(16) float g_agg[(size_t)N_NODES * D];   // mean-agg of x
__device__ __align__(16) float g_h[(size_t)N_NODES * D];     // relu(layer1)
__device__ __align__(16) float g_y2[(size_t)N_NODES * 2];    // h @ W2_l^T

// ---------------- prep: degree histogram, scan, binning ----------------------
__global__ void k_zero_deg() {
    int i = blockIdx.x * blockDim.x + threadIdx.x;
    if (i < N_NODES) g_deg[i] = 0;
}

__global__ void k_hist(const int* __restrict__ ei) {
    int e = blockIdx.x * blockDim.x + threadIdx.x;
    if (e < N_EDGES) {
        int dst = ei[N_EDGES + e];
        if ((unsigned)dst < (unsigned)N_NODES) atomicAdd(&g_deg[dst], 1);
    }
}

__global__ void k_scan() {
    __shared__ int sums[1024];
    int t = threadIdx.x;
    const int CH = (N_NODES + 1023) / 1024;   // 49
    int begin = t * CH;
    int end = begin + CH; if (end > N_NODES) end = N_NODES;
    int s = 0;
    for (int i = begin; i < end; ++i) s += g_deg[i];
    sums[t] = s;
    __syncthreads();
    for (int off = 1; off < 1024; off <<= 1) {
        int v = (t >= off) ? sums[t - off] : 0;
        __syncthreads();
        if (t >= off) sums[t] += v;
        __syncthreads();
    }
    int base = (t == 0) ? 0 : sums[t - 1];
    for (int i = begin; i < end; ++i) {
        g_off[i] = base;
        g_cur[i] = base;
        base += g_deg[i];
    }
    if (t == 1023) g_off[N_NODES] = sums[1023];
}

__global__ void k_bin(const int* __restrict__ ei) {
    int e = blockIdx.x * blockDim.x + threadIdx.x;
    if (e < N_EDGES) {
        int src = ei[e];
        int dst = ei[N_EDGES + e];
        if ((unsigned)dst < (unsigned)N_NODES && (unsigned)src < (unsigned)N_NODES) {
            int p = atomicAdd(&g_cur[dst], 1);
            if ((unsigned)p < (unsigned)N_EDGES) g_ssrc[p] = src;
        }
    }
}

// ---------------- layer-1 aggregation: one warp per node ---------------------
__global__ void k_agg1(const float* __restrict__ x) {
    int w = (blockIdx.x * blockDim.x + threadIdx.x) >> 5;
    int lane = threadIdx.x & 31;
    if (w >= N_NODES) return;
    int beg = g_off[w], end = g_off[w + 1];
    float4 acc = make_float4(0.f, 0.f, 0.f, 0.f);
    const float4* xv = (const float4*)x;
    for (int e = beg; e < end; ++e) {
        int s = g_ssrc[e];
        float4 v = xv[(size_t)s * 32 + lane];
        acc.x += v.x; acc.y += v.y; acc.z += v.z; acc.w += v.w;
    }
    float inv = 1.0f / fmaxf((float)(end - beg), 1.0f);
    float4* o = (float4*)g_agg;
    o[(size_t)w * 32 + lane] = make_float4(acc.x * inv, acc.y * inv, acc.z * inv, acc.w * inv);
}

// ---------------- layer-1 GEMM: h = relu([agg|x] @ [Wl|Wr]^T + b1) -----------
// Static smem only: two 128x32 tiles at stride 33 (conflict-free).
__global__ void __launch_bounds__(256) k_gemm1(
    const float* __restrict__ x,
    const float* __restrict__ Wl, const float* __restrict__ Wr,
    const float* __restrict__ b1)
{
    __shared__ float sA[BM * SSTRIDE];   // input rows (nodes)
    __shared__ float sB[128 * SSTRIDE];  // weight rows (outputs)
    const int tid = threadIdx.x;
    const int m0 = blockIdx.x * BM;
    const int tm = tid >> 4;             // 0..15
    const int tj = tid & 15;             // 0..15

    float acc[8][8];
#pragma unroll
    for (int i = 0; i < 8; ++i)
#pragma unroll
        for (int j = 0; j < 8; ++j) acc[i][j] = 0.f;

    for (int kc = 0; kc < 256; kc += KC) {
        const bool left = (kc < 128);
        const int klocal = left ? kc : (kc - 128);
        // stage input tile: 128 rows x 8 float4
#pragma unroll
        for (int it = 0; it < 4; ++it) {
            int q = tid + it * 256;
            int row = q >> 3, c4 = q & 7;
            int node = m0 + row;
            float4 v = make_float4(0.f, 0.f, 0.f, 0.f);
            if (node < N_NODES) {
                const float* srcp = left ? (g_agg + (size_t)node * D)
                                         : (x + (size_t)node * D);
                v = *(const float4*)(srcp + klocal + c4 * 4);
            }
            float* dst = sA + row * SSTRIDE + c4 * 4;
            dst[0] = v.x; dst[1] = v.y; dst[2] = v.z; dst[3] = v.w;
        }
        // stage weight tile: 128 rows x 8 float4
#pragma unroll
        for (int it = 0; it < 4; ++it) {
            int q = tid + it * 256;
            int row = q >> 3, c4 = q & 7;
            const float* srcp = left ? (Wl + row * D) : (Wr + row * D);
            float4 v = *(const float4*)(srcp + klocal + c4 * 4);
            float* dst = sB + row * SSTRIDE + c4 * 4;
            dst[0] = v.x; dst[1] = v.y; dst[2] = v.z; dst[3] = v.w;
        }
        __syncthreads();

#pragma unroll
        for (int k = 0; k < KC; ++k) {
            float a[8], w[8];
#pragma unroll
            for (int i = 0; i < 8; ++i) a[i] = sA[(tm + 16 * i) * SSTRIDE + k];
#pragma unroll
            for (int j = 0; j < 8; ++j) w[j] = sB[(tj + 16 * j) * SSTRIDE + k];
#pragma unroll
            for (int i = 0; i < 8; ++i)
#pragma unroll
                for (int j = 0; j < 8; ++j) acc[i][j] += a[i] * w[j];
        }
        __syncthreads();
    }

    float bias[8];
#pragma unroll
    for (int j = 0; j < 8; ++j) bias[j] = b1[tj + 16 * j];

#pragma unroll
    for (int i = 0; i < 8; ++i) {
        int node = m0 + tm + 16 * i;
        if (node < N_NODES) {
            float* hp = g_h + (size_t)node * D;
#pragma unroll
            for (int j = 0; j < 8; ++j) {
                float v = acc[i][j] + bias[j];
                hp[tj + 16 * j] = fmaxf(v, 0.f);
            }
        }
    }
}

// ---------------- layer-2: y2 = h@W2_l^T ; out = h@W2_r^T + b2 ---------------
__global__ void k_l2self(const float* __restrict__ W2l,
                         const float* __restrict__ W2r,
                         const float* __restrict__ b2,
                         float* __restrict__ out)
{
    int v = (blockIdx.x * blockDim.x + threadIdx.x) >> 5;
    int lane = threadIdx.x & 31;
    if (v >= N_NODES) return;
    float4 hh = ((const float4*)(g_h + (size_t)v * D))[lane];
    float4 a = ((const float4*)W2l)[lane];            // row 0
    float4 b = ((const float4*)(W2l + D))[lane];      // row 1
    float4 c = ((const float4*)W2r)[lane];
    float4 d = ((const float4*)(W2r + D))[lane];
    float d0 = hh.x * a.x + hh.y * a.y + hh.z * a.z + hh.w * a.w;
    float d1 = hh.x * b.x + hh.y * b.y + hh.z * b.z + hh.w * b.w;
    float d2 = hh.x * c.x + hh.y * c.y + hh.z * c.z + hh.w * c.w;
    float d3 = hh.x * d.x + hh.y * d.y + hh.z * d.z + hh.w * d.w;
#pragma unroll
    for (int o = 16; o > 0; o >>= 1) {
        d0 += __shfl_xor_sync(0xFFFFFFFFu, d0, o);
        d1 += __shfl_xor_sync(0xFFFFFFFFu, d1, o);
        d2 += __shfl_xor_sync(0xFFFFFFFFu, d2, o);
        d3 += __shfl_xor_sync(0xFFFFFFFFu, d3, o);
    }
    if (lane == 0) {
        g_y2[v * 2 + 0] = d0;
        g_y2[v * 2 + 1] = d1;
        out[v * 2 + 0] = d2 + b2[0];
        out[v * 2 + 1] = d3 + b2[1];
    }
}

// ---------------- layer-2 aggregation of y2 (8 bytes/edge) -------------------
__global__ void k_agg2(float* __restrict__ out) {
    int v = (blockIdx.x * blockDim.x + threadIdx.x) >> 5;
    int lane = threadIdx.x & 31;
    if (v >= N_NODES) return;
    int beg = g_off[v], end = g_off[v + 1];
    float a0 = 0.f, a1 = 0.f;
    for (int e = beg + lane; e < end; e += 32) {
        int s = g_ssrc[e];
        float2 y = ((const float2*)g_y2)[s];
        a0 += y.x; a1 += y.y;
    }
#pragma unroll
    for (int o = 16; o > 0; o >>= 1) {
        a0 += __shfl_xor_sync(0xFFFFFFFFu, a0, o);
        a1 += __shfl_xor_sync(0xFFFFFFFFu, a1, o);
    }
    if (lane == 0) {
        float inv = 1.0f / fmaxf((float)(end - beg), 1.0f);
        out[v * 2 + 0] += a0 * inv;
        out[v * 2 + 1] += a1 * inv;
    }
}

// ---------------- launch ------------------------------------------------------
extern "C" void kernel_launch(void* const* d_in, const int* in_sizes, int n_in,
                              void* d_out, int out_size)
{
    const float* x    = (const float*)d_in[0];
    const int*   ei   = (const int*)d_in[1];     // JAX default: int64 demoted to int32
    const float* W1l  = (const float*)d_in[2];
    const float* W1r  = (const float*)d_in[3];
    const float* b1   = (const float*)d_in[4];
    const float* W2l  = (const float*)d_in[5];
    const float* W2r  = (const float*)d_in[6];
    const float* b2   = (const float*)d_in[7];
    float* out = (float*)d_out;

    k_zero_deg<<<(N_NODES + 255) / 256, 256>>>();
    k_hist<<<N_EDGES / 256, 256>>>(ei);
    k_scan<<<1, 1024>>>();
    k_bin<<<N_EDGES / 256, 256>>>(ei);
    k_agg1<<<(N_NODES * 32 + 255) / 256, 256>>>(x);
    k_gemm1<<<(N_NODES + BM - 1) / BM, 256>>>(x, W1l, W1r, b1);
    k_l2self<<<(N_NODES * 32 + 255) / 256, 256>>>(W2l, W2r, b2, out);
    k_agg2<<<(N_NODES * 32 + 255) / 256, 256>>>(out);
}